// round 15
// baseline (speedup 1.0000x reference)
#include <cuda_runtime.h>
#include <cuda_bf16.h>
#include <cuda_fp16.h>
#include <cstdint>
#include <math.h>

#define TT 256
#define BB 16
#define SS 64
#define DD 256
#define SD (SS*DD)          // 16384
#define BSD (BB*SD)         // 262144
#define TBD (TT*BB*DD)      // 1048576

__device__ float g_wxb[TBD];
__device__ float g_red[TT*BB*4*DD];   // partial C-reductions [t][b][sg][e]

// ---------------- helpers ----------------
__device__ __forceinline__ uint32_t smem_u32(const void* p) {
    uint32_t a;
    asm("{ .reg .u64 t; cvta.to.shared.u64 t, %1; cvt.u32.u64 %0, t; }" : "=r"(a) : "l"(p));
    return a;
}
__device__ __forceinline__ float fast_tanh(float x) {
    float ax = fabsf(x);
    float e  = __expf(-2.0f * ax);
    float r  = __fdividef(1.0f - e, 1.0f + e);
    return copysignf(r, x);
}
__device__ __forceinline__ float silu_f(float v) {
    return __fdividef(v, 1.0f + __expf(-v));
}

#define LDSM4(r0, r1, r2, r3, addr) \
    asm volatile("ldmatrix.sync.aligned.m8n8.x4.shared.b16 {%0,%1,%2,%3}, [%4];" \
        : "=r"(r0), "=r"(r1), "=r"(r2), "=r"(r3) : "r"(addr))

#define MMAF16(d, a0, a1, a2, a3, b0, b1) \
    asm volatile("mma.sync.aligned.m16n8k16.row.col.f32.f16.f16.f32 " \
        "{%0,%1,%2,%3}, {%4,%5,%6,%7}, {%8,%9}, {%0,%1,%2,%3};" \
        : "+f"((d)[0]), "+f"((d)[1]), "+f"((d)[2]), "+f"((d)[3]) \
        : "r"(a0), "r"(a1), "r"(a2), "r"(a3), "r"(b0), "r"(b1))

// =====================================================================
// Kernel 1 — prologue: wxb = x@Wx^T + b, h[0] copy.  256 CTAs (proven).
// =====================================================================
__global__ __launch_bounds__(256, 1)
void selman_pre(const float* __restrict__ x, const float* __restrict__ h0,
                const float* __restrict__ Wx, const float* __restrict__ bias,
                float* __restrict__ d_out) {
    extern __shared__ float sm[];
    const int tid = threadIdx.x;
    const int b = blockIdx.x >> 4;
    const int m = blockIdx.x & 15;
    float* h_p = d_out + TBD;

    {   // wxb for t in [16m, 16m+16)
        float* wch = sm;           // [256][68]
        float* xch = sm + 17408;   // [16][64]
        float pacc[16];
        #pragma unroll
        for (int i = 0; i < 16; i++) pacc[i] = 0.0f;
        for (int kt = 0; kt < 4; kt++) {
            const int k0 = kt * 64;
            __syncthreads();
            for (int idx = tid; idx < 256 * 16; idx += 256) {
                int e = idx >> 4, q = idx & 15;
                *(float4*)(wch + e * 68 + q * 4) = *(const float4*)(Wx + e * DD + k0 + q * 4);
            }
            for (int idx = tid; idx < 16 * 16; idx += 256) {
                int i = idx >> 4, q = idx & 15;
                int t = m * 16 + i;
                *(float4*)(xch + i * 64 + q * 4) = *(const float4*)(x + (t * BB + b) * DD + k0 + q * 4);
            }
            __syncthreads();
            for (int q = 0; q < 16; q++) {
                float4 wv = *(const float4*)(wch + tid * 68 + q * 4);
                #pragma unroll
                for (int i = 0; i < 16; i++) {
                    float4 xv = *(const float4*)(xch + i * 64 + q * 4);
                    pacc[i] += wv.x * xv.x + wv.y * xv.y + wv.z * xv.z + wv.w * xv.w;
                }
            }
        }
        float bb = bias[tid];
        #pragma unroll
        for (int i = 0; i < 16; i++) {
            int t = m * 16 + i;
            g_wxb[(t * BB + b) * DD + tid] = pacc[i] + bb;
        }
    }
    // h[0] copy (member m handles s-rows [4m, 4m+4))
    {
        const float* src = h0 + b * SD + (m * 4) * DD;
        float*       dst = h_p + b * SD + (m * 4) * DD;
        for (int idx = tid; idx < 4 * 64; idx += 256) {
            *(float4*)(dst + idx * 4) = *(const float4*)(src + idx * 4);
        }
    }
}

// =====================================================================
// Kernel 2 — fp16 1-pass HMMA recurrence, ZERO cross-CTA communication.
//   64 CTAs x 512 thr (16 warps). CTA m: b = m>>2, sg = m&3,
//   s-rows [16*sg, +16), ALL 256 e-cols. Warp w owns n-slice [16w, 16w+16).
//   Double-buffered local A; one __syncthreads per step. Pipelined tail.
// =====================================================================
#define A_OFF 0
#define A_BUFSZ 8448            // [16 rows][528 B]
#define B_OFF 16896
#define SMEM_MAIN (16896 + 256*528)   // 152064

__global__ __launch_bounds__(512, 1)
void selman_main(const float* __restrict__ Wh, const float* __restrict__ h0,
                 const float* __restrict__ C, float* __restrict__ d_out) {
    extern __shared__ char smc[];
    const int tid  = threadIdx.x;
    const int wid  = tid >> 5;            // 0..15
    const int l    = tid & 31;
    const int m    = blockIdx.x;          // 0..63
    const int b    = m >> 2;
    const int sg   = m & 3;
    const int sbase = sg * 16;
    float* h_p = d_out + TBD;

    // ---- B (full Wh fp16, 256 rows) into padded SMEM ----
    for (int idx = tid; idx < 256 * 256; idx += 512) {
        int n = idx >> 8, k = idx & 255;
        *(__half*)(smc + B_OFF + n * 528 + k * 2) =
            __float2half(Wh[n * DD + k]);
    }
    // ---- A buf0 init from h0 (full 256 k-cols of our 16 rows) ----
    for (int idx = tid; idx < 16 * 256; idx += 512) {
        int row = idx >> 8, k = idx & 255;
        float v = h0[b * SD + (sbase + row) * DD + k];
        *(__half*)(smc + A_OFF + row * 528 + k * 2) = __float2half(v);
    }
    __syncthreads();

    const uint32_t sb = smem_u32(smc);

    // ---- preload B regs: warp w covers weight rows [16w, 16w+16) ----
    const uint32_t brow = (uint32_t)(16 * wid + ((l >> 4) << 3) + (l & 7));
    const uint32_t bk   = (uint32_t)(((l >> 3) & 1) << 3);
    const uint32_t bAddr = sb + B_OFF + brow * 528 + bk * 2;
    uint32_t br[16][4];
    #pragma unroll
    for (int j = 0; j < 16; j++)
        LDSM4(br[j][0], br[j][1], br[j][2], br[j][3], bAddr + (uint32_t)j * 32);

    // ---- A ldmatrix lane address (m16) ----
    const uint32_t arow = (uint32_t)((l & 7) + (((l >> 3) & 1) << 3));
    const uint32_t acol = (uint32_t)((l >> 4) << 3);
    const uint32_t aBase = sb + A_OFF + arow * 528 + acol * 2;

    // ---- epilogue mapping ----
    const int row0 = l >> 2;
    const int eg0  = 16 * wid + 2 * (l & 3);
    const float c0 = C[sbase + row0];
    const float c1 = C[sbase + row0 + 8];

    // previous-step tanh outputs (pipelined off-path tail)
    float pv[8];
    #pragma unroll
    for (int i = 0; i < 8; i++) pv[i] = 0.0f;

    for (int t = 0; t < TT; t++) {
        const int pb = t & 1;

        const float* wp = g_wxb + (t * BB + b) * DD + eg0;
        float2 w0 = __ldg((const float2*)(wp));
        float2 w1 = __ldg((const float2*)(wp + 8));

        const uint32_t aH = aBase + (uint32_t)pb * A_BUFSZ;
        float acc[8];
        #pragma unroll
        for (int i = 0; i < 8; i++) acc[i] = 0.0f;

        // ---- first 8 k-chunks — tensor pipe fills ----
        #pragma unroll
        for (int j = 0; j < 8; j++) {
            const uint32_t ko = (uint32_t)j * 32;
            uint32_t a0, a1, a2, a3;
            LDSM4(a0, a1, a2, a3, aH + ko);
            MMAF16(acc + 0, a0, a1, a2, a3, br[j][0], br[j][1]);
            MMAF16(acc + 4, a0, a1, a2, a3, br[j][2], br[j][3]);
        }

        // ---- pipelined off-path tail for step t-1 (LSU/SHFL under MMA) ----
        if (t > 0) {
            const int tp = t - 1;
            float* hd = h_p + (tp + 1) * BSD + b * SD + sbase * DD;
            *(float2*)(hd + row0 * DD + eg0)           = make_float2(pv[0], pv[1]);
            *(float2*)(hd + row0 * DD + eg0 + 8)       = make_float2(pv[4], pv[5]);
            *(float2*)(hd + (row0 + 8) * DD + eg0)     = make_float2(pv[2], pv[3]);
            *(float2*)(hd + (row0 + 8) * DD + eg0 + 8) = make_float2(pv[6], pv[7]);

            float q0 = pv[0] * c0 + pv[2] * c1;
            float q1 = pv[1] * c0 + pv[3] * c1;
            float q2 = pv[4] * c0 + pv[6] * c1;
            float q3 = pv[5] * c0 + pv[7] * c1;
            #pragma unroll
            for (int d = 4; d < 32; d <<= 1) {
                q0 += __shfl_xor_sync(0xffffffffu, q0, d);
                q1 += __shfl_xor_sync(0xffffffffu, q1, d);
                q2 += __shfl_xor_sync(0xffffffffu, q2, d);
                q3 += __shfl_xor_sync(0xffffffffu, q3, d);
            }
            if (l < 4) {
                float* rp = g_red + (((tp * BB + b) * 4 + sg) * DD)
                          + 16 * wid + 2 * l;
                *(float2*)(rp)     = make_float2(q0, q1);
                *(float2*)(rp + 8) = make_float2(q2, q3);
            }
        }

        // ---- remaining 8 k-chunks ----
        #pragma unroll
        for (int j = 8; j < 16; j++) {
            const uint32_t ko = (uint32_t)j * 32;
            uint32_t a0, a1, a2, a3;
            LDSM4(a0, a1, a2, a3, aH + ko);
            MMAF16(acc + 0, a0, a1, a2, a3, br[j][0], br[j][1]);
            MMAF16(acc + 4, a0, a1, a2, a3, br[j][2], br[j][3]);
        }

        // ---- critical epilogue: tanh + pack + local A(t+1) store ----
        const uint32_t nbOff = (uint32_t)(pb ^ 1) * A_BUFSZ;

        float v00 = fast_tanh(acc[0] + w0.x);
        float v01 = fast_tanh(acc[1] + w0.y);
        float v02 = fast_tanh(acc[2] + w0.x);
        float v03 = fast_tanh(acc[3] + w0.y);
        float v10 = fast_tanh(acc[4] + w1.x);
        float v11 = fast_tanh(acc[5] + w1.y);
        float v12 = fast_tanh(acc[6] + w1.x);
        float v13 = fast_tanh(acc[7] + w1.y);

        {
            __half2 H0 = __floats2half2_rn(v00, v01);
            __half2 H1 = __floats2half2_rn(v02, v03);
            __half2 H2 = __floats2half2_rn(v10, v11);
            __half2 H3 = __floats2half2_rn(v12, v13);
            uint32_t uH0 = *(uint32_t*)&H0, uH1 = *(uint32_t*)&H1;
            uint32_t uH2 = *(uint32_t*)&H2, uH3 = *(uint32_t*)&H3;

            uint32_t o00 = nbOff + (uint32_t)(row0 * 528 + eg0 * 2);
            uint32_t o01 = o00 + 16;                 // +8 cols
            uint32_t o10 = nbOff + (uint32_t)((row0 + 8) * 528 + eg0 * 2);
            uint32_t o11 = o10 + 16;
            *(uint32_t*)(smc + A_OFF + o00) = uH0;
            *(uint32_t*)(smc + A_OFF + o01) = uH2;
            *(uint32_t*)(smc + A_OFF + o10) = uH1;
            *(uint32_t*)(smc + A_OFF + o11) = uH3;
        }

        __syncthreads();      // A(t+1) visible to all 16 warps

        // carry tanh outputs into next iteration's hidden tail
        pv[0] = v00; pv[1] = v01; pv[2] = v02; pv[3] = v03;
        pv[4] = v10; pv[5] = v11; pv[6] = v12; pv[7] = v13;
    }

    // ---- flush final off-path tail (t = TT-1) ----
    {
        const int tp = TT - 1;
        float* hd = h_p + (tp + 1) * BSD + b * SD + sbase * DD;
        *(float2*)(hd + row0 * DD + eg0)           = make_float2(pv[0], pv[1]);
        *(float2*)(hd + row0 * DD + eg0 + 8)       = make_float2(pv[4], pv[5]);
        *(float2*)(hd + (row0 + 8) * DD + eg0)     = make_float2(pv[2], pv[3]);
        *(float2*)(hd + (row0 + 8) * DD + eg0 + 8) = make_float2(pv[6], pv[7]);

        float q0 = pv[0] * c0 + pv[2] * c1;
        float q1 = pv[1] * c0 + pv[3] * c1;
        float q2 = pv[4] * c0 + pv[6] * c1;
        float q3 = pv[5] * c0 + pv[7] * c1;
        #pragma unroll
        for (int d = 4; d < 32; d <<= 1) {
            q0 += __shfl_xor_sync(0xffffffffu, q0, d);
            q1 += __shfl_xor_sync(0xffffffffu, q1, d);
            q2 += __shfl_xor_sync(0xffffffffu, q2, d);
            q3 += __shfl_xor_sync(0xffffffffu, q3, d);
        }
        if (l < 4) {
            float* rp = g_red + (((tp * BB + b) * 4 + sg) * DD)
                      + 16 * wid + 2 * l;
            *(float2*)(rp)     = make_float2(q0, q1);
            *(float2*)(rp + 8) = make_float2(q2, q3);
        }
    }
}

// =====================================================================
// Kernel 3 — out[t][b][e] = (sum of 4 partials) * silu(z)
// =====================================================================
__global__ __launch_bounds__(256, 1)
void selman_fin(const float* __restrict__ z, float* __restrict__ d_out) {
    const int tb = blockIdx.x;           // t*BB + b
    const int e  = threadIdx.x;
    const float* rp = g_red + tb * 4 * DD + e;
    float s = rp[0] + rp[DD] + rp[2 * DD] + rp[3 * DD];
    int o = tb * DD + e;
    d_out[o] = s * silu_f(z[o]);
}

extern "C" void kernel_launch(void* const* d_in, const int* in_sizes, int n_in,
                              void* d_out, int out_size) {
    const float* x    = (const float*)d_in[0];
    const float* z    = (const float*)d_in[1];
    const float* h0   = (const float*)d_in[2];
    const float* Wx   = (const float*)d_in[3];
    const float* Wh   = (const float*)d_in[4];
    const float* bias = (const float*)d_in[5];
    const float* C    = (const float*)d_in[6];
    float* out = (float*)d_out;

    size_t smem_pre = 18432 * sizeof(float);
    cudaFuncSetAttribute(selman_pre, cudaFuncAttributeMaxDynamicSharedMemorySize, (int)smem_pre);
    cudaFuncSetAttribute(selman_main, cudaFuncAttributeMaxDynamicSharedMemorySize, SMEM_MAIN);

    selman_pre<<<256, 256, smem_pre>>>(x, h0, Wx, bias, out);
    selman_main<<<64, 512, SMEM_MAIN>>>(Wh, h0, C, out);
    selman_fin<<<TT * BB, 256>>>(z, out);
}

// round 16
// speedup vs baseline: 1.0574x; 1.0574x over previous
#include <cuda_runtime.h>
#include <cuda_bf16.h>
#include <cuda_fp16.h>
#include <cstdint>
#include <math.h>

#define TT 256
#define BB 16
#define SS 64
#define DD 256
#define SD (SS*DD)          // 16384
#define BSD (BB*SD)         // 262144
#define TBD (TT*BB*DD)      // 1048576

__device__ float g_wxb[TBD];
__device__ float g_red[TT*BB*4*DD];   // partial C-reductions [t][b][sg][e]

// ---------------- helpers ----------------
__device__ __forceinline__ uint32_t smem_u32(const void* p) {
    uint32_t a;
    asm("{ .reg .u64 t; cvta.to.shared.u64 t, %1; cvt.u32.u64 %0, t; }" : "=r"(a) : "l"(p));
    return a;
}
// Rational tanh without abs/copysign: safe since |x| << 44 here.
// E = exp(2x); tanh = (E-1)/(E+1).  ~6 instr, ~44-cyc chain.
__device__ __forceinline__ float fast_tanh(float x) {
    float E = __expf(2.0f * x);
    return __fdividef(E - 1.0f, E + 1.0f);
}
__device__ __forceinline__ float silu_f(float v) {
    return __fdividef(v, 1.0f + __expf(-v));
}

#define LDSM4(r0, r1, r2, r3, addr) \
    asm volatile("ldmatrix.sync.aligned.m8n8.x4.shared.b16 {%0,%1,%2,%3}, [%4];" \
        : "=r"(r0), "=r"(r1), "=r"(r2), "=r"(r3) : "r"(addr))

#define MMAF16(d, a0, a1, a2, a3, b0, b1) \
    asm volatile("mma.sync.aligned.m16n8k16.row.col.f32.f16.f16.f32 " \
        "{%0,%1,%2,%3}, {%4,%5,%6,%7}, {%8,%9}, {%0,%1,%2,%3};" \
        : "+f"((d)[0]), "+f"((d)[1]), "+f"((d)[2]), "+f"((d)[3]) \
        : "r"(a0), "r"(a1), "r"(a2), "r"(a3), "r"(b0), "r"(b1))

#define CLUSTER_ARRIVE() asm volatile("barrier.cluster.arrive.aligned;" ::: "memory")
#define CLUSTER_WAIT()   asm volatile("barrier.cluster.wait.aligned;" ::: "memory")
#define STS_CLUSTER(addr, val) \
    asm volatile("st.shared::cluster.u32 [%0], %1;" :: "r"(addr), "r"(val) : "memory")

// =====================================================================
// Kernel 1 — prologue: wxb = x@Wx^T + b, h[0] copy.  256 CTAs (proven).
// =====================================================================
__global__ __launch_bounds__(256, 1)
void selman_pre(const float* __restrict__ x, const float* __restrict__ h0,
                const float* __restrict__ Wx, const float* __restrict__ bias,
                float* __restrict__ d_out) {
    extern __shared__ float sm[];
    const int tid = threadIdx.x;
    const int b = blockIdx.x >> 4;
    const int m = blockIdx.x & 15;
    float* h_p = d_out + TBD;

    {   // wxb for t in [16m, 16m+16)
        float* wch = sm;           // [256][68]
        float* xch = sm + 17408;   // [16][64]
        float pacc[16];
        #pragma unroll
        for (int i = 0; i < 16; i++) pacc[i] = 0.0f;
        for (int kt = 0; kt < 4; kt++) {
            const int k0 = kt * 64;
            __syncthreads();
            for (int idx = tid; idx < 256 * 16; idx += 256) {
                int e = idx >> 4, q = idx & 15;
                *(float4*)(wch + e * 68 + q * 4) = *(const float4*)(Wx + e * DD + k0 + q * 4);
            }
            for (int idx = tid; idx < 16 * 16; idx += 256) {
                int i = idx >> 4, q = idx & 15;
                int t = m * 16 + i;
                *(float4*)(xch + i * 64 + q * 4) = *(const float4*)(x + (t * BB + b) * DD + k0 + q * 4);
            }
            __syncthreads();
            for (int q = 0; q < 16; q++) {
                float4 wv = *(const float4*)(wch + tid * 68 + q * 4);
                #pragma unroll
                for (int i = 0; i < 16; i++) {
                    float4 xv = *(const float4*)(xch + i * 64 + q * 4);
                    pacc[i] += wv.x * xv.x + wv.y * xv.y + wv.z * xv.z + wv.w * xv.w;
                }
            }
        }
        float bb = bias[tid];
        #pragma unroll
        for (int i = 0; i < 16; i++) {
            int t = m * 16 + i;
            g_wxb[(t * BB + b) * DD + tid] = pacc[i] + bb;
        }
    }
    // h[0] copy (member m handles s-rows [4m, 4m+4))
    {
        const float* src = h0 + b * SD + (m * 4) * DD;
        float*       dst = h_p + b * SD + (m * 4) * DD;
        for (int idx = tid; idx < 4 * 64; idx += 256) {
            *(float4*)(dst + idx * 4) = *(const float4*)(src + idx * 4);
        }
    }
}

// =====================================================================
// Kernel 2 — fp16 1-pass HMMA recurrence, split cluster barrier,
//   send-first epilogue, cross-iteration pipelined off-path tail.
//   128 CTAs x 256 thr, cluster 2.  (R14 structure, leaner tanh.)
// =====================================================================
#define A_OFF 0
#define A_BUFSZ 8448            // [16 rows][528 B]
#define B_OFF 16896
#define SMEM_MAIN 84480         // 16896 + 128*528

__global__ __launch_bounds__(256, 1) __cluster_dims__(2, 1, 1)
void selman_main(const float* __restrict__ Wh, const float* __restrict__ h0,
                 const float* __restrict__ C, float* __restrict__ d_out) {
    extern __shared__ char smc[];
    const int tid  = threadIdx.x;
    const int wid  = tid >> 5;
    const int l    = tid & 31;
    const int rg   = blockIdx.x >> 1;     // 0..63
    const int rank = blockIdx.x & 1;      // e-half
    const int b    = rg >> 2;
    const int sg   = rg & 3;
    const int sbase = sg * 16;
    float* h_p = d_out + TBD;

    // ---- B (Wh fp16) into padded SMEM ----
    for (int idx = tid; idx < 128 * 256; idx += 256) {
        int n = idx >> 8, k = idx & 255;
        *(__half*)(smc + B_OFF + n * 528 + k * 2) =
            __float2half(Wh[(128 * rank + n) * DD + k]);
    }
    // ---- A buf0 init from h0 (full 256 k-cols of our 16 rows) ----
    for (int idx = tid; idx < 16 * 256; idx += 256) {
        int row = idx >> 8, k = idx & 255;
        float v = h0[b * SD + (sbase + row) * DD + k];
        *(__half*)(smc + A_OFF + row * 528 + k * 2) = __float2half(v);
    }
    __syncthreads();

    const uint32_t sb = smem_u32(smc);

    // ---- preload B regs: br[0..7] = own-half k-chunks, br[8..15] = peer ----
    const uint32_t brow = (uint32_t)(16 * wid + ((l >> 4) << 3) + (l & 7));
    const uint32_t bk   = (uint32_t)(((l >> 3) & 1) << 3);
    const uint32_t bAddr = sb + B_OFF + brow * 528 + bk * 2;
    const uint32_t ownOff  = (uint32_t)(rank * 256);
    const uint32_t peerOff = (uint32_t)((rank ^ 1) * 256);
    uint32_t br[16][4];
    #pragma unroll
    for (int j = 0; j < 8; j++)
        LDSM4(br[j][0], br[j][1], br[j][2], br[j][3], bAddr + ownOff + (uint32_t)j * 32);
    #pragma unroll
    for (int j = 0; j < 8; j++)
        LDSM4(br[8+j][0], br[8+j][1], br[8+j][2], br[8+j][3], bAddr + peerOff + (uint32_t)j * 32);

    // ---- A ldmatrix lane address (m16) ----
    const uint32_t arow = (uint32_t)((l & 7) + (((l >> 3) & 1) << 3));
    const uint32_t acol = (uint32_t)((l >> 4) << 3);
    const uint32_t aBase = sb + A_OFF + arow * 528 + acol * 2;

    // ---- peer A base via mapa ----
    uint32_t peerA;
    asm("mapa.shared::cluster.u32 %0, %1, %2;"
        : "=r"(peerA) : "r"(sb + A_OFF), "r"(rank ^ 1));

    // ---- epilogue mapping ----
    const int row0 = l >> 2;
    const int eg0  = 128 * rank + 16 * wid + 2 * (l & 3);
    const float c0 = C[sbase + row0];
    const float c1 = C[sbase + row0 + 8];

    // previous-step tanh outputs (pipelined off-path tail)
    float pv[8];
    #pragma unroll
    for (int i = 0; i < 8; i++) pv[i] = 0.0f;

    CLUSTER_ARRIVE();     // matches first in-loop WAIT

    for (int t = 0; t < TT; t++) {
        const int pb = t & 1;

        const float* wp = g_wxb + (t * BB + b) * DD + eg0;
        float2 w0 = __ldg((const float2*)(wp));
        float2 w1 = __ldg((const float2*)(wp + 8));

        const uint32_t aH = aBase + (uint32_t)pb * A_BUFSZ;
        float acc[8];
        #pragma unroll
        for (int i = 0; i < 8; i++) acc[i] = 0.0f;

        // ---- own-half k-chunks (local data) — tensor pipe fills up ----
        #pragma unroll
        for (int j = 0; j < 8; j++) {
            const uint32_t ko = ownOff + (uint32_t)j * 32;
            uint32_t a0, a1, a2, a3;
            LDSM4(a0, a1, a2, a3, aH + ko);
            MMAF16(acc + 0, a0, a1, a2, a3, br[j][0], br[j][1]);
            MMAF16(acc + 4, a0, a1, a2, a3, br[j][2], br[j][3]);
        }

        // ---- pipelined off-path tail for step t-1 (LSU/SHFL under MMA) ----
        if (t > 0) {
            const int tp = t - 1;
            float* hd = h_p + (tp + 1) * BSD + b * SD + sbase * DD;
            *(float2*)(hd + row0 * DD + eg0)           = make_float2(pv[0], pv[1]);
            *(float2*)(hd + row0 * DD + eg0 + 8)       = make_float2(pv[4], pv[5]);
            *(float2*)(hd + (row0 + 8) * DD + eg0)     = make_float2(pv[2], pv[3]);
            *(float2*)(hd + (row0 + 8) * DD + eg0 + 8) = make_float2(pv[6], pv[7]);

            float q0 = pv[0] * c0 + pv[2] * c1;
            float q1 = pv[1] * c0 + pv[3] * c1;
            float q2 = pv[4] * c0 + pv[6] * c1;
            float q3 = pv[5] * c0 + pv[7] * c1;
            #pragma unroll
            for (int d = 4; d < 32; d <<= 1) {
                q0 += __shfl_xor_sync(0xffffffffu, q0, d);
                q1 += __shfl_xor_sync(0xffffffffu, q1, d);
                q2 += __shfl_xor_sync(0xffffffffu, q2, d);
                q3 += __shfl_xor_sync(0xffffffffu, q3, d);
            }
            if (l < 4) {
                float* rp = g_red + (((tp * BB + b) * 4 + sg) * DD)
                          + 128 * rank + 16 * wid + 2 * l;
                *(float2*)(rp)     = make_float2(q0, q1);
                *(float2*)(rp + 8) = make_float2(q2, q3);
            }
        }

        CLUSTER_WAIT();   // peer's DSMEM writes for buf[pb] now visible

        // ---- peer-half k-chunks ----
        #pragma unroll
        for (int j = 0; j < 8; j++) {
            const uint32_t ko = peerOff + (uint32_t)j * 32;
            uint32_t a0, a1, a2, a3;
            LDSM4(a0, a1, a2, a3, aH + ko);
            MMAF16(acc + 0, a0, a1, a2, a3, br[8+j][0], br[8+j][1]);
            MMAF16(acc + 4, a0, a1, a2, a3, br[8+j][2], br[8+j][3]);
        }

        // ---- epilogue: SEND-FIRST critical segment ----
        const uint32_t nbOff = (uint32_t)(pb ^ 1) * A_BUFSZ;

        float v00 = fast_tanh(acc[0] + w0.x);
        float v01 = fast_tanh(acc[1] + w0.y);
        float v02 = fast_tanh(acc[2] + w0.x);
        float v03 = fast_tanh(acc[3] + w0.y);
        float v10 = fast_tanh(acc[4] + w1.x);
        float v11 = fast_tanh(acc[5] + w1.y);
        float v12 = fast_tanh(acc[6] + w1.x);
        float v13 = fast_tanh(acc[7] + w1.y);

        {
            __half2 H0 = __floats2half2_rn(v00, v01);
            __half2 H1 = __floats2half2_rn(v02, v03);
            __half2 H2 = __floats2half2_rn(v10, v11);
            __half2 H3 = __floats2half2_rn(v12, v13);
            uint32_t uH0 = *(uint32_t*)&H0, uH1 = *(uint32_t*)&H1;
            uint32_t uH2 = *(uint32_t*)&H2, uH3 = *(uint32_t*)&H3;

            uint32_t o00 = nbOff + (uint32_t)(row0 * 528 + eg0 * 2);
            uint32_t o01 = o00 + 16;                 // +8 cols
            uint32_t o10 = nbOff + (uint32_t)((row0 + 8) * 528 + eg0 * 2);
            uint32_t o11 = o10 + 16;
            STS_CLUSTER(peerA + o00, uH0);
            STS_CLUSTER(peerA + o01, uH2);
            STS_CLUSTER(peerA + o10, uH1);
            STS_CLUSTER(peerA + o11, uH3);
            *(uint32_t*)(smc + A_OFF + o00) = uH0;
            *(uint32_t*)(smc + A_OFF + o01) = uH2;
            *(uint32_t*)(smc + A_OFF + o10) = uH1;
            *(uint32_t*)(smc + A_OFF + o11) = uH3;
        }

        __syncthreads();      // local + DSMEM A(t+1) stores issued by all threads
        CLUSTER_ARRIVE();     // release; peer can start its next step

        // carry tanh outputs into next iteration's hidden tail
        pv[0] = v00; pv[1] = v01; pv[2] = v02; pv[3] = v03;
        pv[4] = v10; pv[5] = v11; pv[6] = v12; pv[7] = v13;
    }

    // ---- flush final off-path tail (t = TT-1) ----
    {
        const int tp = TT - 1;
        float* hd = h_p + (tp + 1) * BSD + b * SD + sbase * DD;
        *(float2*)(hd + row0 * DD + eg0)           = make_float2(pv[0], pv[1]);
        *(float2*)(hd + row0 * DD + eg0 + 8)       = make_float2(pv[4], pv[5]);
        *(float2*)(hd + (row0 + 8) * DD + eg0)     = make_float2(pv[2], pv[3]);
        *(float2*)(hd + (row0 + 8) * DD + eg0 + 8) = make_float2(pv[6], pv[7]);

        float q0 = pv[0] * c0 + pv[2] * c1;
        float q1 = pv[1] * c0 + pv[3] * c1;
        float q2 = pv[4] * c0 + pv[6] * c1;
        float q3 = pv[5] * c0 + pv[7] * c1;
        #pragma unroll
        for (int d = 4; d < 32; d <<= 1) {
            q0 += __shfl_xor_sync(0xffffffffu, q0, d);
            q1 += __shfl_xor_sync(0xffffffffu, q1, d);
            q2 += __shfl_xor_sync(0xffffffffu, q2, d);
            q3 += __shfl_xor_sync(0xffffffffu, q3, d);
        }
        if (l < 4) {
            float* rp = g_red + (((tp * BB + b) * 4 + sg) * DD)
                      + 128 * rank + 16 * wid + 2 * l;
            *(float2*)(rp)     = make_float2(q0, q1);
            *(float2*)(rp + 8) = make_float2(q2, q3);
        }
    }
    CLUSTER_WAIT();           // balance final arrive
}

// =====================================================================
// Kernel 3 — out[t][b][e] = (sum of 4 partials) * silu(z)
// =====================================================================
__global__ __launch_bounds__(256, 1)
void selman_fin(const float* __restrict__ z, float* __restrict__ d_out) {
    const int tb = blockIdx.x;           // t*BB + b
    const int e  = threadIdx.x;
    const float* rp = g_red + tb * 4 * DD + e;
    float s = rp[0] + rp[DD] + rp[2 * DD] + rp[3 * DD];
    int o = tb * DD + e;
    d_out[o] = s * silu_f(z[o]);
}

extern "C" void kernel_launch(void* const* d_in, const int* in_sizes, int n_in,
                              void* d_out, int out_size) {
    const float* x    = (const float*)d_in[0];
    const float* z    = (const float*)d_in[1];
    const float* h0   = (const float*)d_in[2];
    const float* Wx   = (const float*)d_in[3];
    const float* Wh   = (const float*)d_in[4];
    const float* bias = (const float*)d_in[5];
    const float* C    = (const float*)d_in[6];
    float* out = (float*)d_out;

    size_t smem_pre = 18432 * sizeof(float);
    cudaFuncSetAttribute(selman_pre, cudaFuncAttributeMaxDynamicSharedMemorySize, (int)smem_pre);
    cudaFuncSetAttribute(selman_main, cudaFuncAttributeMaxDynamicSharedMemorySize, SMEM_MAIN);

    selman_pre<<<256, 256, smem_pre>>>(x, h0, Wx, bias, out);
    selman_main<<<128, 256, SMEM_MAIN>>>(Wh, h0, C, out);
    selman_fin<<<TT * BB, 256>>>(z, out);
}